// round 1
// baseline (speedup 1.0000x reference)
#include <cuda_runtime.h>
#include <math.h>

#define B_ 4096
#define M_ 4
#define D_ 512
#define N_ ((M_ + 1) * B_)   // 20480

// Scratch (static device globals — no allocation at runtime)
__device__ float g_all[(size_t)N_ * D_];   // normalized [orig; masked] rows, 40 MB
__device__ float g_denom[B_];
__device__ float g_loss_sum;

__device__ __forceinline__ float get_temp(int it) {
    if (it >= 300000) return 0.05f;
    float progress = (float)it / 300000.0f;
    return 0.05f + 0.5f * (0.2f - 0.05f) * (1.0f + cosf(3.14159265358979323846f * progress));
}

// ---------------------------------------------------------------------------
// Kernel 1: L2-normalize every row of [orig; masked] into g_all.
// Also zeroes g_denom / g_loss_sum (deterministic per-launch init).
// grid = N_ blocks, 128 threads; each thread handles one float4 (512/4/128).
// ---------------------------------------------------------------------------
__global__ void normalize_kernel(const float* __restrict__ orig,
                                 const float* __restrict__ masked) {
    int row = blockIdx.x;
    const float* src = (row < B_) ? (orig + (size_t)row * D_)
                                  : (masked + (size_t)(row - B_) * D_);
    int t = threadIdx.x;  // 0..127
    float4 v = ((const float4*)src)[t];
    float s = v.x * v.x + v.y * v.y + v.z * v.z + v.w * v.w;
    #pragma unroll
    for (int off = 16; off > 0; off >>= 1)
        s += __shfl_down_sync(0xffffffffu, s, off);
    __shared__ float sm[4];
    __shared__ float s_inv;
    if ((t & 31) == 0) sm[t >> 5] = s;
    __syncthreads();
    if (t == 0) {
        float tot = sm[0] + sm[1] + sm[2] + sm[3];
        s_inv = 1.0f / fmaxf(sqrtf(tot), 1e-12f);
        if (row < B_) g_denom[row] = 0.0f;
        if (row == 0) g_loss_sum = 0.0f;
    }
    __syncthreads();
    float inv = s_inv;
    float4 o = make_float4(v.x * inv, v.y * inv, v.z * inv, v.w * inv);
    ((float4*)(g_all + (size_t)row * D_))[t] = o;
}

// ---------------------------------------------------------------------------
// Kernel 2: fused exp-GEMM. For each (i in [0,B), j in [0,N)):
//   acc = dot(g_all[i], g_all[j]); contribute (j==i ? 0 : exp(acc/T)) to denom[i].
// 128x128 block tile, BK=8, 8x8 register tile per thread, 256 threads.
// ---------------------------------------------------------------------------
#define BM 128
#define BN 128
#define BK 8
#define TM 8
#define TN 8

__global__ __launch_bounds__(256, 2) void gemm_exp_kernel(const int* __restrict__ d_iter) {
    __shared__ float As[BK][BM];
    __shared__ float Bs[BK][BN];
    const int rowBase = blockIdx.y * BM;
    const int colBase = blockIdx.x * BN;
    const int tid = threadIdx.x;
    const int tx = tid & 15;   // 16 col groups
    const int ty = tid >> 4;   // 16 row groups
    const int lrow = tid >> 1;         // 0..127: tile row this thread loads
    const int lcol = (tid & 1) * 4;    // 0 or 4: k-segment

    const float* Ag = g_all + (size_t)(rowBase + lrow) * D_ + lcol;
    const float* Bg = g_all + (size_t)(colBase + lrow) * D_ + lcol;

    float acc[TM][TN];
    #pragma unroll
    for (int i = 0; i < TM; i++)
        #pragma unroll
        for (int j = 0; j < TN; j++) acc[i][j] = 0.0f;

    for (int k0 = 0; k0 < D_; k0 += BK) {
        float4 a4 = *(const float4*)(Ag + k0);
        float4 b4 = *(const float4*)(Bg + k0);
        __syncthreads();   // previous iteration's compute done before overwrite
        As[lcol + 0][lrow] = a4.x; As[lcol + 1][lrow] = a4.y;
        As[lcol + 2][lrow] = a4.z; As[lcol + 3][lrow] = a4.w;
        Bs[lcol + 0][lrow] = b4.x; Bs[lcol + 1][lrow] = b4.y;
        Bs[lcol + 2][lrow] = b4.z; Bs[lcol + 3][lrow] = b4.w;
        __syncthreads();
        #pragma unroll
        for (int k = 0; k < BK; k++) {
            float a[TM], b[TN];
            *(float4*)&a[0] = *(const float4*)&As[k][ty * TM];
            *(float4*)&a[4] = *(const float4*)&As[k][ty * TM + 4];
            *(float4*)&b[0] = *(const float4*)&Bs[k][tx * TN];
            *(float4*)&b[4] = *(const float4*)&Bs[k][tx * TN + 4];
            #pragma unroll
            for (int i = 0; i < TM; i++)
                #pragma unroll
                for (int j = 0; j < TN; j++)
                    acc[i][j] = fmaf(a[i], b[j], acc[i][j]);
        }
    }

    const float invT = 1.0f / get_temp(d_iter[0]);
    #pragma unroll
    for (int i = 0; i < TM; i++) {
        const int gi = rowBase + ty * TM + i;
        float rsum = 0.0f;
        #pragma unroll
        for (int j = 0; j < TN; j++) {
            const int gj = colBase + tx * TN + j;
            float e = __expf(acc[i][j] * invT);
            rsum += (gj == gi) ? 0.0f : e;
        }
        // reduce across the 16 tx lanes (width-16 segments align with tx groups)
        #pragma unroll
        for (int off = 8; off > 0; off >>= 1)
            rsum += __shfl_down_sync(0xffffffffu, rsum, off, 16);
        if (tx == 0) atomicAdd(&g_denom[gi], rsum);
    }
}

// ---------------------------------------------------------------------------
// Kernel 3: positives + per-row loss. One block per row i (128 threads).
// pos_i = sum_m exp(dot(orig_i, masked_{m,i})/T); loss_i = log(denom+1e-8)-log(pos)
// ---------------------------------------------------------------------------
__global__ void pos_loss_kernel(const int* __restrict__ d_iter) {
    const int i = blockIdx.x;
    const int t = threadIdx.x;  // 0..127
    const float4 qv = ((const float4*)(g_all + (size_t)i * D_))[t];
    float p[M_];
    #pragma unroll
    for (int m = 0; m < M_; m++) {
        const float4 kv = ((const float4*)(g_all + (size_t)((m + 1) * B_ + i) * D_))[t];
        p[m] = qv.x * kv.x + qv.y * kv.y + qv.z * kv.z + qv.w * kv.w;
    }
    __shared__ float sm[M_][4];
    #pragma unroll
    for (int m = 0; m < M_; m++) {
        float v = p[m];
        #pragma unroll
        for (int off = 16; off > 0; off >>= 1)
            v += __shfl_down_sync(0xffffffffu, v, off);
        if ((t & 31) == 0) sm[m][t >> 5] = v;
    }
    __syncthreads();
    if (t == 0) {
        const float invT = 1.0f / get_temp(d_iter[0]);
        float pos = 0.0f;
        #pragma unroll
        for (int m = 0; m < M_; m++) {
            float d = sm[m][0] + sm[m][1] + sm[m][2] + sm[m][3];
            pos += __expf(d * invT);
        }
        const float denom = g_denom[i];
        const float loss = logf(denom + 1e-8f) - logf(pos);
        atomicAdd(&g_loss_sum, loss);
    }
}

__global__ void finalize_kernel(float* __restrict__ out) {
    out[0] = g_loss_sum * (1.0f / (float)B_);
}

// ---------------------------------------------------------------------------
extern "C" void kernel_launch(void* const* d_in, const int* in_sizes, int n_in,
                              void* d_out, int out_size) {
    const float* orig   = (const float*)d_in[0];
    const float* masked = (const float*)d_in[1];
    const int*   iter   = (const int*)d_in[2];
    float* out = (float*)d_out;

    normalize_kernel<<<N_, 128>>>(orig, masked);
    gemm_exp_kernel<<<dim3(N_ / BN, B_ / BM), 256>>>(iter);
    pos_loss_kernel<<<B_, 128>>>(iter);
    finalize_kernel<<<1, 1>>>(out);
}

// round 3
// speedup vs baseline: 6.7224x; 6.7224x over previous
#include <cuda_runtime.h>
#include <cuda_bf16.h>
#include <math.h>
#include <stdint.h>

#define B_ 4096
#define M_ 4
#define D_ 512
#define N_ ((M_ + 1) * B_)   // 20480

// Static device scratch (no runtime allocation)
__device__ __nv_bfloat16 g_bf16[(size_t)N_ * D_];   // normalized rows, bf16, 20 MB
__device__ float g_denom[B_];
__device__ float g_loss_sum;

__device__ __forceinline__ float get_temp(int it) {
    if (it >= 300000) return 0.05f;
    float progress = (float)it / 300000.0f;
    return 0.05f + 0.5f * (0.2f - 0.05f) * (1.0f + cosf(3.14159265358979323846f * progress));
}

__device__ __forceinline__ uint32_t smem_u32(const void* p) {
    uint32_t a;
    asm("{ .reg .u64 t; cvta.to.shared.u64 t, %1; cvt.u32.u64 %0, t; }" : "=r"(a) : "l"(p));
    return a;
}

__device__ __forceinline__ uint32_t swz128(uint32_t off) {
    return off ^ ((off >> 3) & 0x70);
}

#define CP_ASYNC16(dst, src) \
    asm volatile("cp.async.cg.shared.global [%0], [%1], 16;" :: "r"(dst), "l"(src) : "memory")
#define CP_COMMIT() asm volatile("cp.async.commit_group;" ::: "memory")

#define LDMATRIX_X4(r0, r1, r2, r3, addr) \
    asm volatile("ldmatrix.sync.aligned.m8n8.x4.shared.b16 {%0,%1,%2,%3}, [%4];" \
                 : "=r"(r0), "=r"(r1), "=r"(r2), "=r"(r3) : "r"(addr))

#define MMA_BF16(d, a, b0, b1) \
    asm volatile("mma.sync.aligned.m16n8k16.row.col.f32.bf16.bf16.f32 " \
                 "{%0,%1,%2,%3}, {%4,%5,%6,%7}, {%8,%9}, {%0,%1,%2,%3};" \
                 : "+f"((d)[0]), "+f"((d)[1]), "+f"((d)[2]), "+f"((d)[3]) \
                 : "r"((a)[0]), "r"((a)[1]), "r"((a)[2]), "r"((a)[3]), \
                   "r"(b0), "r"(b1))

// ---------------------------------------------------------------------------
// Kernel 1: L2-normalize every row into g_bf16; zero accumulators.
// ---------------------------------------------------------------------------
__global__ void normalize_kernel(const float* __restrict__ orig,
                                 const float* __restrict__ masked) {
    int row = blockIdx.x;
    const float* src = (row < B_) ? (orig + (size_t)row * D_)
                                  : (masked + (size_t)(row - B_) * D_);
    int t = threadIdx.x;  // 0..127
    float4 v = ((const float4*)src)[t];
    float s = v.x * v.x + v.y * v.y + v.z * v.z + v.w * v.w;
    #pragma unroll
    for (int off = 16; off > 0; off >>= 1)
        s += __shfl_down_sync(0xffffffffu, s, off);
    __shared__ float sm[4];
    __shared__ float s_inv;
    if ((t & 31) == 0) sm[t >> 5] = s;
    __syncthreads();
    if (t == 0) {
        float tot = sm[0] + sm[1] + sm[2] + sm[3];
        s_inv = 1.0f / fmaxf(sqrtf(tot), 1e-12f);
        if (row < B_) g_denom[row] = 0.0f;
        if (row == 0) g_loss_sum = 0.0f;
    }
    __syncthreads();
    float inv = s_inv;
    __nv_bfloat162 lo = __floats2bfloat162_rn(v.x * inv, v.y * inv);
    __nv_bfloat162 hi = __floats2bfloat162_rn(v.z * inv, v.w * inv);
    __nv_bfloat162* dst = (__nv_bfloat162*)(g_bf16 + (size_t)row * D_);
    dst[2 * t]     = lo;
    dst[2 * t + 1] = hi;
}

// ---------------------------------------------------------------------------
// Kernel 2: HMMA (mma.sync bf16) exp-GEMM.
// Tile 128x128, 8 warps (warp = 64x32), K=512 in 8 chunks of 64 (128 B rows).
// 3-stage cp.async pipeline, SW128-swizzled SMEM, ldmatrix fragment loads.
// ---------------------------------------------------------------------------
#define TILE 128
#define NCHUNK 8
#define NSTAGE 3
#define STG_A_SZ (TILE * 128)   // 16 KB
#define STG_B_SZ (TILE * 128)   // 16 KB
#define SMEM_A_OFF 1024
#define SMEM_B_OFF (SMEM_A_OFF + NSTAGE * STG_A_SZ)
#define SMEM_TOTAL (SMEM_B_OFF + NSTAGE * STG_B_SZ)   // 99328 B

__device__ __forceinline__ void load_chunk(int chunk, int stage, uint32_t sb,
                                           const char* gA, const char* gB, int tid) {
    // 256 threads; each loads 4 x 16B of A and 4 x 16B of B.
    const int row = tid >> 1;
    const int kb0 = (tid & 1) * 64;
    const char* asrc = gA + (size_t)row * 1024 + chunk * 128 + kb0;
    const char* bsrc = gB + (size_t)row * 1024 + chunk * 128 + kb0;
    const uint32_t abase = sb + SMEM_A_OFF + stage * STG_A_SZ;
    const uint32_t bbase = sb + SMEM_B_OFF + stage * STG_B_SZ;
    #pragma unroll
    for (int c = 0; c < 4; c++) {
        uint32_t off = (uint32_t)row * 128 + kb0 + c * 16;
        CP_ASYNC16(abase + swz128(off), asrc + c * 16);
        CP_ASYNC16(bbase + swz128(off), bsrc + c * 16);
    }
}

__global__ __launch_bounds__(256, 2) void gemm_hmma_kernel(const int* __restrict__ d_iter) {
    extern __shared__ __align__(1024) char smem[];
    float* sdenom = (float*)smem;   // 128 floats at offset 0
    uint32_t sb = smem_u32(smem);

    const int tid  = threadIdx.x;
    const int wid  = tid >> 5;
    const int lane = tid & 31;
    const int warpM = wid & 1;        // 0/1 -> 64 rows each
    const int warpN = wid >> 1;       // 0..3 -> 32 cols each
    const int rowBase = blockIdx.y * TILE;
    const int colBase = blockIdx.x * TILE;
    const char* gA = (const char*)(g_bf16 + (size_t)rowBase * D_);
    const char* gB = (const char*)(g_bf16 + (size_t)colBase * D_);

    if (tid < TILE) sdenom[tid] = 0.0f;

    load_chunk(0, 0, sb, gA, gB, tid); CP_COMMIT();
    load_chunk(1, 1, sb, gA, gB, tid); CP_COMMIT();

    float acc[4][4][4];
    #pragma unroll
    for (int mt = 0; mt < 4; mt++)
        #pragma unroll
        for (int nt = 0; nt < 4; nt++)
            #pragma unroll
            for (int f = 0; f < 4; f++) acc[mt][nt][f] = 0.0f;

    // per-lane fragment offset components
    const int a_row = warpM * 64 + (lane & 15);            // + mt*16
    const int a_kb  = (lane >> 4) * 16;                    // + kk*32
    const int b_row = warpN * 32 + ((lane >> 4) << 3) + (lane & 7);  // + ntp*16
    const int b_kb  = ((lane >> 3) & 1) * 16;              // + kk*32

    #pragma unroll
    for (int k = 0; k < NCHUNK; k++) {
        if (k < NCHUNK - 1) asm volatile("cp.async.wait_group 1;" ::: "memory");
        else                asm volatile("cp.async.wait_group 0;" ::: "memory");
        __syncthreads();
        if (k + 2 < NCHUNK) {
            load_chunk(k + 2, (k + 2) % NSTAGE, sb, gA, gB, tid);
            CP_COMMIT();
        }

        const int st = k % NSTAGE;
        const uint32_t Ab = sb + SMEM_A_OFF + st * STG_A_SZ;
        const uint32_t Bb = sb + SMEM_B_OFF + st * STG_B_SZ;

        #pragma unroll
        for (int kk = 0; kk < 4; kk++) {
            uint32_t a[4][4];
            #pragma unroll
            for (int mt = 0; mt < 4; mt++) {
                uint32_t off = (uint32_t)(a_row + mt * 16) * 128 + kk * 32 + a_kb;
                LDMATRIX_X4(a[mt][0], a[mt][1], a[mt][2], a[mt][3], Ab + swz128(off));
            }
            uint32_t b[2][4];
            #pragma unroll
            for (int ntp = 0; ntp < 2; ntp++) {
                uint32_t off = (uint32_t)(b_row + ntp * 16) * 128 + kk * 32 + b_kb;
                LDMATRIX_X4(b[ntp][0], b[ntp][1], b[ntp][2], b[ntp][3], Bb + swz128(off));
            }
            #pragma unroll
            for (int mt = 0; mt < 4; mt++)
                #pragma unroll
                for (int nt = 0; nt < 4; nt++)
                    MMA_BF16(acc[mt][nt], a[mt], b[nt >> 1][(nt & 1) * 2],
                             b[nt >> 1][(nt & 1) * 2 + 1]);
        }
    }

    // Epilogue: exp, diag mask, row sums
    const float invT = 1.0f / get_temp(d_iter[0]);
    #pragma unroll
    for (int mt = 0; mt < 4; mt++) {
        const int r0 = warpM * 64 + mt * 16 + (lane >> 2);  // local row
        const int gi0 = rowBase + r0;
        const int gi1 = gi0 + 8;
        float rs0 = 0.0f, rs1 = 0.0f;
        #pragma unroll
        for (int nt = 0; nt < 4; nt++) {
            const int col = colBase + warpN * 32 + nt * 8 + 2 * (lane & 3);
            float e0 = __expf(acc[mt][nt][0] * invT);
            float e1 = __expf(acc[mt][nt][1] * invT);
            float e2 = __expf(acc[mt][nt][2] * invT);
            float e3 = __expf(acc[mt][nt][3] * invT);
            if (col != gi0)     rs0 += e0;
            if (col + 1 != gi0) rs0 += e1;
            if (col != gi1)     rs1 += e2;
            if (col + 1 != gi1) rs1 += e3;
        }
        rs0 += __shfl_xor_sync(0xffffffffu, rs0, 1);
        rs0 += __shfl_xor_sync(0xffffffffu, rs0, 2);
        rs1 += __shfl_xor_sync(0xffffffffu, rs1, 1);
        rs1 += __shfl_xor_sync(0xffffffffu, rs1, 2);
        if ((lane & 3) == 0) {
            atomicAdd(&sdenom[r0], rs0);
            atomicAdd(&sdenom[r0 + 8], rs1);
        }
    }
    __syncthreads();
    if (tid < TILE) atomicAdd(&g_denom[rowBase + tid], sdenom[tid]);
}

// ---------------------------------------------------------------------------
// Kernel 3: positives + per-row loss (bf16 inputs, fp32 dots).
// ---------------------------------------------------------------------------
__global__ void pos_loss_kernel(const int* __restrict__ d_iter) {
    const int i = blockIdx.x;
    const int t = threadIdx.x;  // 0..127, 4 bf16 elems each
    const __nv_bfloat162* q = (const __nv_bfloat162*)(g_bf16 + (size_t)i * D_);
    __nv_bfloat162 q0 = q[2 * t], q1 = q[2 * t + 1];
    float2 qa = __bfloat1622float2(q0), qb = __bfloat1622float2(q1);
    float p[M_];
    #pragma unroll
    for (int m = 0; m < M_; m++) {
        const __nv_bfloat162* kv =
            (const __nv_bfloat162*)(g_bf16 + (size_t)((m + 1) * B_ + i) * D_);
        float2 ka = __bfloat1622float2(kv[2 * t]);
        float2 kb = __bfloat1622float2(kv[2 * t + 1]);
        p[m] = qa.x * ka.x + qa.y * ka.y + qb.x * kb.x + qb.y * kb.y;
    }
    __shared__ float sm[M_][4];
    #pragma unroll
    for (int m = 0; m < M_; m++) {
        float v = p[m];
        #pragma unroll
        for (int off = 16; off > 0; off >>= 1)
            v += __shfl_down_sync(0xffffffffu, v, off);
        if ((t & 31) == 0) sm[m][t >> 5] = v;
    }
    __syncthreads();
    if (t == 0) {
        const float invT = 1.0f / get_temp(d_iter[0]);
        float pos = 0.0f;
        #pragma unroll
        for (int m = 0; m < M_; m++) {
            float d = sm[m][0] + sm[m][1] + sm[m][2] + sm[m][3];
            pos += __expf(d * invT);
        }
        const float denom = g_denom[i];
        const float loss = logf(denom + 1e-8f) - logf(pos);
        atomicAdd(&g_loss_sum, loss);
    }
}

__global__ void finalize_kernel(float* __restrict__ out) {
    out[0] = g_loss_sum * (1.0f / (float)B_);
}

// ---------------------------------------------------------------------------
extern "C" void kernel_launch(void* const* d_in, const int* in_sizes, int n_in,
                              void* d_out, int out_size) {
    const float* orig   = (const float*)d_in[0];
    const float* masked = (const float*)d_in[1];
    const int*   iter   = (const int*)d_in[2];
    float* out = (float*)d_out;

    cudaFuncSetAttribute(gemm_hmma_kernel,
                         cudaFuncAttributeMaxDynamicSharedMemorySize, SMEM_TOTAL);

    normalize_kernel<<<N_, 128>>>(orig, masked);
    gemm_hmma_kernel<<<dim3(N_ / TILE, B_ / TILE), 256, SMEM_TOTAL>>>(iter);
    pos_loss_kernel<<<B_, 128>>>(iter);
    finalize_kernel<<<1, 1>>>(out);
}